// round 6
// baseline (speedup 1.0000x reference)
#include <cuda_runtime.h>
#include <math.h>

#define N_ATOMS 2048
#define HID     32
#define CUTOFF  2.5f
#define CUTOFF2 6.25f
#define JCHUNK  16
#define LUT_N   4096
#define NPART   64          // energy partial slots
#define NGROUP  32          // done-counter groups (1024 blocks / 32)

__device__ double   g_part[NPART];
__device__ unsigned g_done1[NGROUP];
__device__ unsigned g_done2 = 0;
__device__ float2   g_lut[LUT_N];

__device__ __forceinline__ float tanh_fast(float x) {
    float y;
    asm("tanh.approx.f32 %0, %1;" : "=f"(y) : "f"(x));
    return y;
}
__device__ __forceinline__ float sqrt_fast(float x) {
    float y;
    asm("sqrt.approx.f32 %0, %1;" : "=f"(y) : "f"(x));
    return y;
}

// LUT of f(d) = sum_k W2[k]*tanh(W1[k]*d + b1[k]) + b2 on [0, CUTOFF].
// Entry i stores (f(x_i), f(x_{i+1}) - f(x_i)) for single-load lerp.
__global__ __launch_bounds__(256) void lut_kernel(
    const float* __restrict__ W1, const float* __restrict__ b1,
    const float* __restrict__ W2, const float* __restrict__ b2)
{
    const int idx = blockIdx.x * blockDim.x + threadIdx.x;
    if (idx >= LUT_N) return;
    const float dx = CUTOFF / (float)LUT_N;
    const float x0 = (float)idx * dx;
    const float x1 = x0 + dx;
    float f0 = b2[0], f1 = f0;
    #pragma unroll
    for (int k = 0; k < HID; k++) {
        float w1 = W1[k], bb = b1[k], w2 = W2[k];
        f0 = fmaf(tanh_fast(fmaf(x0, w1, bb)), w2, f0);
        f1 = fmaf(tanh_fast(fmaf(x1, w1, bb)), w2, f1);
    }
    g_lut[idx] = make_float2(f0, f1 - f0);
}

__global__ __launch_bounds__(256) void pair_kernel(
    const float* __restrict__ xyz,
    const float* __restrict__ cell,
    float* __restrict__ out)
{
    __shared__ float4 sj[JCHUNK];
    __shared__ float  swarp[8];

    const int tid = threadIdx.x;
    const int blk = blockIdx.x + gridDim.x * blockIdx.y;
    const int i   = blockIdx.x * 256 + tid;         // 8 i-tiles
    const int j0  = blockIdx.y * JCHUNK;            // 128 j-groups

    if (tid < JCHUNK) {
        int j = j0 + tid;
        sj[tid] = make_float4(xyz[3*j], xyz[3*j+1], xyz[3*j+2], 0.f);
    }
    __syncthreads();

    const float Lx = cell[0], Ly = cell[1], Lz = cell[2];
    const float iLx = 1.0f / Lx, iLy = 1.0f / Ly, iLz = 1.0f / Lz;
    const float xi = xyz[3*i], yi = xyz[3*i+1], zi = xyz[3*i+2];
    const float lscale = (float)LUT_N / CUTOFF;

    float acc = 0.0f;

    #pragma unroll
    for (int jj = 0; jj < JCHUNK; jj++) {
        float4 p = sj[jj];
        float dx = p.x - xi;
        float dy = p.y - yi;
        float dz = p.z - zi;
        dx = fmaf(-Lx, rintf(dx * iLx), dx);
        dy = fmaf(-Ly, rintf(dy * iLy), dy);
        dz = fmaf(-Lz, rintf(dz * iLz), dz);
        float dsq = fmaf(dx, dx, fmaf(dy, dy, dz * dz));

        bool ok  = (dsq > 0.0f) && (dsq < CUTOFF2);
        float ds = ok ? dsq : 1.0f;
        float dist = sqrt_fast(ds);
        float t  = dist * lscale;             // < 4096
        int   it = (int)t;
        float fr = t - (float)it;
        float2 e = __ldg(&g_lut[it]);
        float v  = fmaf(fr, e.y, e.x);
        acc += ok ? v : 0.0f;
    }

    // warp reduce in float
    #pragma unroll
    for (int off = 16; off > 0; off >>= 1)
        acc += __shfl_down_sync(0xFFFFFFFFu, acc, off);

    const int lane = tid & 31;
    const int warp = tid >> 5;
    if (lane == 0) swarp[warp] = acc;
    __syncthreads();

    if (warp == 0) {
        float v = (lane < 8) ? swarp[lane] : 0.0f;
        #pragma unroll
        for (int off = 4; off > 0; off >>= 1)
            v += __shfl_down_sync(0xFFFFFFFFu, v, off);

        if (lane == 0) {
            // 64-way spread energy accumulation (parallel at L2)
            atomicAdd(&g_part[blk & (NPART - 1)], (double)v);
            __threadfence();
            // two-level done counter: max 32-deep same-address chains
            unsigned o1 = atomicAdd(&g_done1[blk >> 5], 1u);
            if (o1 == 31u) {                       // last of this 32-block group
                __threadfence();
                unsigned o2 = atomicAdd(&g_done2, 1u);
                if (o2 == NGROUP - 1u) {           // globally last block
                    __threadfence();
                    double esum = 0.0;
                    #pragma unroll
                    for (int p = 0; p < NPART; p++)
                        esum += g_part[p];
                    out[0] = (float)(0.5 * esum);  // ordered pairs double-count
                    // reset state for next graph replay
                    #pragma unroll
                    for (int p = 0; p < NPART; p++)
                        g_part[p] = 0.0;
                    #pragma unroll
                    for (int p = 0; p < NGROUP; p++)
                        g_done1[p] = 0u;
                    __threadfence();
                    g_done2 = 0u;
                }
            }
        }
    }
}

extern "C" void kernel_launch(void* const* d_in, const int* in_sizes, int n_in,
                              void* d_out, int out_size)
{
    const float* xyz  = (const float*)d_in[0];
    const float* cell = (const float*)d_in[1];
    const float* W1   = (const float*)d_in[2];
    const float* b1   = (const float*)d_in[3];
    const float* W2   = (const float*)d_in[4];
    const float* b2   = (const float*)d_in[5];
    float* out = (float*)d_out;

    lut_kernel<<<LUT_N / 256, 256>>>(W1, b1, W2, b2);
    dim3 grid(N_ATOMS / 256, N_ATOMS / JCHUNK);   // 8 x 128 = 1024 blocks
    pair_kernel<<<grid, 256>>>(xyz, cell, out);
}

// round 7
// speedup vs baseline: 1.4125x; 1.4125x over previous
#include <cuda_runtime.h>
#include <math.h>

#define N_ATOMS 2048
#define HID     32
#define CUTOFF  2.5f
#define CUTOFF2 6.25f
#define JCHUNK  32
#define LUT_N   4096          // bins over dsq in [0, CUTOFF2]; +1 guard bin

__device__ double   g_energy = 0.0;
__device__ unsigned g_done   = 0;
__device__ float2   g_lut[LUT_N + 1];

__device__ __forceinline__ float tanh_fast(float x) {
    float y;
    asm("tanh.approx.f32 %0, %1;" : "=f"(y) : "f"(x));
    return y;
}
__device__ __forceinline__ float sqrt_fast(float x) {
    float y;
    asm("sqrt.approx.f32 %0, %1;" : "=f"(y) : "f"(x));
    return y;
}

// LUT over s = dsq: entry i = ( f(sqrt(s_i)), f(sqrt(s_{i+1})) - f(sqrt(s_i)) ).
// Guard entry LUT_N = (0,0): clamped misses contribute exactly zero.
__global__ __launch_bounds__(256) void lut_kernel(
    const float* __restrict__ W1, const float* __restrict__ b1,
    const float* __restrict__ W2, const float* __restrict__ b2)
{
    const int idx = blockIdx.x * blockDim.x + threadIdx.x;
    if (idx > LUT_N) return;
    if (idx == LUT_N) {
        g_lut[idx] = make_float2(0.f, 0.f);
        return;
    }
    const float ds = CUTOFF2 / (float)LUT_N;
    const float d0 = sqrt_fast((float)idx * ds);
    const float d1 = sqrt_fast((float)(idx + 1) * ds);
    float f0 = b2[0], f1 = f0;
    #pragma unroll
    for (int k = 0; k < HID; k++) {
        float w1 = W1[k], bb = b1[k], w2 = W2[k];
        f0 = fmaf(tanh_fast(fmaf(d0, w1, bb)), w2, f0);
        f1 = fmaf(tanh_fast(fmaf(d1, w1, bb)), w2, f1);
    }
    g_lut[idx] = make_float2(f0, f1 - f0);
}

__global__ __launch_bounds__(256, 4) void pair_kernel(
    const float* __restrict__ xyz,
    const float* __restrict__ cell,
    float* __restrict__ out)
{
    __shared__ float4 sj[JCHUNK];
    __shared__ float  swarp[8];

    const int tid = threadIdx.x;
    const int i   = blockIdx.x * 256 + tid;       // 8 i-tiles
    const int j0  = blockIdx.y * JCHUNK;          // 64 j-groups

    if (tid < JCHUNK) {
        int j = j0 + tid;
        sj[tid] = make_float4(xyz[3*j], xyz[3*j+1], xyz[3*j+2], 0.f);
    }
    __syncthreads();

    const float Lx = cell[0], Ly = cell[1], Lz = cell[2];
    const float iLx = 1.0f / Lx, iLy = 1.0f / Ly, iLz = 1.0f / Lz;
    const float xi = xyz[3*i], yi = xyz[3*i+1], zi = xyz[3*i+2];
    const float sscale = (float)LUT_N / CUTOFF2;   // dsq -> bin
    const float tmax   = (float)LUT_N;             // guard bin

    float acc = 0.0f;

    #pragma unroll
    for (int jj = 0; jj < JCHUNK; jj++) {
        float4 p = sj[jj];
        float dx = p.x - xi;
        float dy = p.y - yi;
        float dz = p.z - zi;
        dx = fmaf(-Lx, rintf(dx * iLx), dx);
        dy = fmaf(-Ly, rintf(dy * iLy), dy);
        dz = fmaf(-Lz, rintf(dz * iLz), dz);
        float dsq = fmaf(dx, dx, fmaf(dy, dy, dz * dz));

        float t  = fminf(dsq * sscale, tmax);   // miss -> guard bin (0,0)
        int   it = (int)t;
        float fr = t - (float)it;
        float2 e = __ldg(&g_lut[it]);
        acc += fmaf(fr, e.y, e.x);              // unconditional
    }

    // self-pair correction: dsq=0 hit bin 0 and contributed f(0)
    if ((unsigned)(i - j0) < (unsigned)JCHUNK)
        acc -= __ldg(&g_lut[0]).x;

    // warp reduce in float
    #pragma unroll
    for (int off = 16; off > 0; off >>= 1)
        acc += __shfl_down_sync(0xFFFFFFFFu, acc, off);

    const int lane = tid & 31;
    const int warp = tid >> 5;
    if (lane == 0) swarp[warp] = acc;
    __syncthreads();

    if (warp == 0) {
        float v = (lane < 8) ? swarp[lane] : 0.0f;
        #pragma unroll
        for (int off = 4; off > 0; off >>= 1)
            v += __shfl_down_sync(0xFFFFFFFFu, v, off);
        if (lane == 0) {
            atomicAdd(&g_energy, (double)v);
            __threadfence();
            unsigned total = gridDim.x * gridDim.y;
            unsigned old = atomicAdd(&g_done, 1u);
            if (old == total - 1) {
                __threadfence();
                double esum = __longlong_as_double(
                    atomicExch((unsigned long long*)&g_energy, 0ULL));
                out[0] = (float)(0.5 * esum);   // ordered pairs double-count
                __threadfence();
                atomicExch(&g_done, 0u);
            }
        }
    }
}

extern "C" void kernel_launch(void* const* d_in, const int* in_sizes, int n_in,
                              void* d_out, int out_size)
{
    const float* xyz  = (const float*)d_in[0];
    const float* cell = (const float*)d_in[1];
    const float* W1   = (const float*)d_in[2];
    const float* b1   = (const float*)d_in[3];
    const float* W2   = (const float*)d_in[4];
    const float* b2   = (const float*)d_in[5];
    float* out = (float*)d_out;

    lut_kernel<<<(LUT_N + 1 + 255) / 256, 256>>>(W1, b1, W2, b2);
    dim3 grid(N_ATOMS / 256, N_ATOMS / JCHUNK);   // 8 x 64 = 512 blocks
    pair_kernel<<<grid, 256>>>(xyz, cell, out);
}

// round 8
// speedup vs baseline: 1.6069x; 1.1376x over previous
#include <cuda_runtime.h>
#include <math.h>

#define N_ATOMS 2048
#define HID     32
#define CUTOFF  2.5f
#define CUTOFF2 6.25f
#define JCHUNK  16
#define LUT_N   4096          // bins over dsq in [0, CUTOFF2]; +1 guard bin
#define NDIAG   128           // 8 diagonal tiles x 16 chunks, weight 0.5
#define NBLK    576           // 128 diag + 448 off-diag

__device__ double   g_energy = 0.0;
__device__ unsigned g_done   = 0;
__device__ float2   g_lut[LUT_N + 1];

// cumulative off-diagonal chunk counts per i-tile (count ti = 112 - 16*ti)
__constant__ int c_off[9] = {0, 112, 208, 288, 352, 400, 432, 448, 448};

__device__ __forceinline__ float tanh_fast(float x) {
    float y;
    asm("tanh.approx.f32 %0, %1;" : "=f"(y) : "f"(x));
    return y;
}
__device__ __forceinline__ float sqrt_fast(float x) {
    float y;
    asm("sqrt.approx.f32 %0, %1;" : "=f"(y) : "f"(x));
    return y;
}

// LUT over s = dsq: entry i = ( f(sqrt(s_i)), f(sqrt(s_{i+1})) - f(sqrt(s_i)) ).
// Guard entry LUT_N = (0,0): clamped misses contribute exactly zero.
__global__ __launch_bounds__(256) void lut_kernel(
    const float* __restrict__ W1, const float* __restrict__ b1,
    const float* __restrict__ W2, const float* __restrict__ b2)
{
    const int idx = blockIdx.x * blockDim.x + threadIdx.x;
    if (idx > LUT_N) return;
    if (idx == LUT_N) {
        g_lut[idx] = make_float2(0.f, 0.f);
        return;
    }
    const float ds = CUTOFF2 / (float)LUT_N;
    const float d0 = sqrt_fast((float)idx * ds);
    const float d1 = sqrt_fast((float)(idx + 1) * ds);
    float f0 = b2[0], f1 = f0;
    #pragma unroll
    for (int k = 0; k < HID; k++) {
        float w1 = W1[k], bb = b1[k], w2 = W2[k];
        f0 = fmaf(tanh_fast(fmaf(d0, w1, bb)), w2, f0);
        f1 = fmaf(tanh_fast(fmaf(d1, w1, bb)), w2, f1);
    }
    g_lut[idx] = make_float2(f0, f1 - f0);
}

__global__ __launch_bounds__(256, 4) void pair_kernel(
    const float* __restrict__ xyz,
    const float* __restrict__ cell,
    float* __restrict__ out)
{
    __shared__ float4 sj[JCHUNK];
    __shared__ float  swarp[8];

    const int tid = threadIdx.x;
    const int blk = blockIdx.x;

    // ---- block -> (i_tile, j0, weight) -------------------------------
    int   ti, j0;
    float w;
    if (blk < NDIAG) {                    // diagonal band: full 256x16, w=0.5
        ti = blk >> 4;
        j0 = ti * 256 + (blk & 15) * JCHUNK;
        w  = 0.5f;
    } else {                              // strictly above the diagonal, w=1
        int b = blk - NDIAG;
        ti = 0;
        #pragma unroll
        for (int k = 0; k < 7; k++)
            if (b >= c_off[k + 1]) ti = k + 1;
        j0 = (ti + 1) * 256 + (b - c_off[ti]) * JCHUNK;
        w  = 1.0f;
    }
    const int i = ti * 256 + tid;

    if (tid < JCHUNK) {
        int j = j0 + tid;
        sj[tid] = make_float4(xyz[3*j], xyz[3*j+1], xyz[3*j+2], 0.f);
    }
    __syncthreads();

    const float Lx = cell[0], Ly = cell[1], Lz = cell[2];
    const float xi = xyz[3*i], yi = xyz[3*i+1], zi = xyz[3*i+2];
    const float sscale = (float)LUT_N / CUTOFF2;   // dsq -> bin
    const float tmax   = (float)LUT_N;             // guard bin

    float acc = 0.0f;

    #pragma unroll
    for (int jj = 0; jj < JCHUNK; jj++) {
        float4 p = sj[jj];
        // MIC magnitude per dim: |dx_mic| = min(|dx|, L - |dx|)  (|dx| < L)
        float ax = fabsf(p.x - xi);
        float ay = fabsf(p.y - yi);
        float az = fabsf(p.z - zi);
        float wx = fminf(ax, Lx - ax);
        float wy = fminf(ay, Ly - ay);
        float wz = fminf(az, Lz - az);
        float dsq = fmaf(wx, wx, fmaf(wy, wy, wz * wz));

        float t  = fminf(dsq * sscale, tmax);   // miss -> guard bin (0,0)
        int   it = (int)t;
        float fr = t - (float)it;
        float2 e = __ldg(&g_lut[it]);
        acc += fmaf(fr, e.y, e.x);              // unconditional
    }

    // self-pair (dsq = 0, bin 0) appears once per atom, in its diag chunk
    if ((unsigned)(i - j0) < (unsigned)JCHUNK)
        acc -= __ldg(&g_lut[0]).x;

    acc *= w;

    // warp reduce in float
    #pragma unroll
    for (int off = 16; off > 0; off >>= 1)
        acc += __shfl_down_sync(0xFFFFFFFFu, acc, off);

    const int lane = tid & 31;
    const int warp = tid >> 5;
    if (lane == 0) swarp[warp] = acc;
    __syncthreads();

    if (warp == 0) {
        float v = (lane < 8) ? swarp[lane] : 0.0f;
        #pragma unroll
        for (int off = 4; off > 0; off >>= 1)
            v += __shfl_down_sync(0xFFFFFFFFu, v, off);
        if (lane == 0) {
            atomicAdd(&g_energy, (double)v);
            __threadfence();
            unsigned old = atomicAdd(&g_done, 1u);
            if (old == NBLK - 1) {
                __threadfence();
                double esum = __longlong_as_double(
                    atomicExch((unsigned long long*)&g_energy, 0ULL));
                out[0] = (float)esum;          // triangle: no halving
                __threadfence();
                atomicExch(&g_done, 0u);
            }
        }
    }
}

extern "C" void kernel_launch(void* const* d_in, const int* in_sizes, int n_in,
                              void* d_out, int out_size)
{
    const float* xyz  = (const float*)d_in[0];
    const float* cell = (const float*)d_in[1];
    const float* W1   = (const float*)d_in[2];
    const float* b1   = (const float*)d_in[3];
    const float* W2   = (const float*)d_in[4];
    const float* b2   = (const float*)d_in[5];
    float* out = (float*)d_out;

    lut_kernel<<<(LUT_N + 1 + 255) / 256, 256>>>(W1, b1, W2, b2);
    pair_kernel<<<NBLK, 256>>>(xyz, cell, out);
}

// round 9
// speedup vs baseline: 1.6350x; 1.0175x over previous
#include <cuda_runtime.h>
#include <math.h>

#define N_ATOMS 2048
#define HID     32
#define CUTOFF  2.5f
#define CUTOFF2 6.25f
#define JCHUNK  16
#define LUT_N   4096          // bins over dsq in [0, CUTOFF2]; +1 guard bin
#define NDIAG   128           // 8 diagonal tiles x 16 chunks, weight 0.5
#define NBLK    576           // 128 diag + 448 off-diag

__device__ double   g_energy = 0.0;
__device__ unsigned g_done   = 0;
__device__ float2   g_lut[LUT_N + 1];

// cumulative off-diagonal chunk counts per i-tile (count ti = 112 - 16*ti)
__constant__ int c_off[9] = {0, 112, 208, 288, 352, 400, 432, 448, 448};

__device__ __forceinline__ float tanh_fast(float x) {
    float y;
    asm("tanh.approx.f32 %0, %1;" : "=f"(y) : "f"(x));
    return y;
}
__device__ __forceinline__ float sqrt_fast(float x) {
    float y;
    asm("sqrt.approx.f32 %0, %1;" : "=f"(y) : "f"(x));
    return y;
}

// LUT over s = dsq: entry i = ( f(sqrt(s_i)), f(sqrt(s_{i+1})) - f(sqrt(s_i)) ).
// Guard entry LUT_N = (0,0): clamped misses contribute exactly zero.
__global__ __launch_bounds__(256) void lut_kernel(
    const float* __restrict__ W1, const float* __restrict__ b1,
    const float* __restrict__ W2, const float* __restrict__ b2)
{
    const int idx = blockIdx.x * blockDim.x + threadIdx.x;
    if (idx <= LUT_N) {
        if (idx == LUT_N) {
            g_lut[idx] = make_float2(0.f, 0.f);
        } else {
            const float ds = CUTOFF2 / (float)LUT_N;
            const float d0 = sqrt_fast((float)idx * ds);
            const float d1 = sqrt_fast((float)(idx + 1) * ds);
            float f0 = b2[0], f1 = f0;
            #pragma unroll
            for (int k = 0; k < HID; k++) {
                float w1 = W1[k], bb = b1[k], w2 = W2[k];
                f0 = fmaf(tanh_fast(fmaf(d0, w1, bb)), w2, f0);
                f1 = fmaf(tanh_fast(fmaf(d1, w1, bb)), w2, f1);
            }
            g_lut[idx] = make_float2(f0, f1 - f0);
        }
    }
    // Writes visible, then release the PDL-gated consumer grid early.
    __threadfence();
    cudaTriggerProgrammaticLaunchCompletion();
}

__global__ __launch_bounds__(256, 4) void pair_kernel(
    const float* __restrict__ xyz,
    const float* __restrict__ cell,
    float* __restrict__ out)
{
    __shared__ float4 sj[JCHUNK];
    __shared__ float  swarp[8];

    const int tid = threadIdx.x;
    const int blk = blockIdx.x;

    // ---- block -> (i_tile, j0, weight) -------------------------------
    int   ti, j0;
    float w;
    if (blk < NDIAG) {                    // diagonal band: full 256x16, w=0.5
        ti = blk >> 4;
        j0 = ti * 256 + (blk & 15) * JCHUNK;
        w  = 0.5f;
    } else {                              // strictly above the diagonal, w=1
        int b = blk - NDIAG;
        ti = 0;
        #pragma unroll
        for (int k = 0; k < 7; k++)
            if (b >= c_off[k + 1]) ti = k + 1;
        j0 = (ti + 1) * 256 + (b - c_off[ti]) * JCHUNK;
        w  = 1.0f;
    }
    const int i = ti * 256 + tid;

    // Prologue: runs concurrently with lut_kernel (no g_lut dependence).
    if (tid < JCHUNK) {
        int j = j0 + tid;
        sj[tid] = make_float4(xyz[3*j], xyz[3*j+1], xyz[3*j+2], 0.f);
    }
    const float Lx = cell[0], Ly = cell[1], Lz = cell[2];
    const float xi = xyz[3*i], yi = xyz[3*i+1], zi = xyz[3*i+2];
    __syncthreads();

    // Wait for lut_kernel's triggered writes before any g_lut read.
    cudaGridDependencySynchronize();

    const float sscale = (float)LUT_N / CUTOFF2;   // dsq -> bin
    const float tmax   = (float)LUT_N;             // guard bin

    float acc = 0.0f;

    #pragma unroll
    for (int jj = 0; jj < JCHUNK; jj++) {
        float4 p = sj[jj];
        // MIC magnitude per dim: |dx_mic| = min(|dx|, L - |dx|)  (|dx| < L)
        float ax = fabsf(p.x - xi);
        float ay = fabsf(p.y - yi);
        float az = fabsf(p.z - zi);
        float wx = fminf(ax, Lx - ax);
        float wy = fminf(ay, Ly - ay);
        float wz = fminf(az, Lz - az);
        float dsq = fmaf(wx, wx, fmaf(wy, wy, wz * wz));

        float t  = fminf(dsq * sscale, tmax);   // miss -> guard bin (0,0)
        int   it = (int)t;
        float fr = t - (float)it;
        float2 e = __ldg(&g_lut[it]);
        acc += fmaf(fr, e.y, e.x);              // unconditional
    }

    // self-pair (dsq = 0, bin 0) appears once per atom, in its diag chunk
    if ((unsigned)(i - j0) < (unsigned)JCHUNK)
        acc -= __ldg(&g_lut[0]).x;

    acc *= w;

    // warp reduce in float
    #pragma unroll
    for (int off = 16; off > 0; off >>= 1)
        acc += __shfl_down_sync(0xFFFFFFFFu, acc, off);

    const int lane = tid & 31;
    const int warp = tid >> 5;
    if (lane == 0) swarp[warp] = acc;
    __syncthreads();

    if (warp == 0) {
        float v = (lane < 8) ? swarp[lane] : 0.0f;
        #pragma unroll
        for (int off = 4; off > 0; off >>= 1)
            v += __shfl_down_sync(0xFFFFFFFFu, v, off);
        if (lane == 0) {
            atomicAdd(&g_energy, (double)v);
            __threadfence();
            unsigned old = atomicAdd(&g_done, 1u);
            if (old == NBLK - 1) {
                __threadfence();
                double esum = __longlong_as_double(
                    atomicExch((unsigned long long*)&g_energy, 0ULL));
                out[0] = (float)esum;          // triangle: no halving
                __threadfence();
                atomicExch(&g_done, 0u);
            }
        }
    }
}

extern "C" void kernel_launch(void* const* d_in, const int* in_sizes, int n_in,
                              void* d_out, int out_size)
{
    const float* xyz  = (const float*)d_in[0];
    const float* cell = (const float*)d_in[1];
    const float* W1   = (const float*)d_in[2];
    const float* b1   = (const float*)d_in[3];
    const float* W2   = (const float*)d_in[4];
    const float* b2   = (const float*)d_in[5];
    float* out = (float*)d_out;

    lut_kernel<<<(LUT_N + 1 + 255) / 256, 256>>>(W1, b1, W2, b2);

    // PDL: pair_kernel pre-launches while lut_kernel runs; its CTAs block at
    // cudaGridDependencySynchronize() until lut triggers completion.
    cudaLaunchConfig_t cfg = {};
    cfg.gridDim  = dim3(NBLK, 1, 1);
    cfg.blockDim = dim3(256, 1, 1);
    cfg.dynamicSmemBytes = 0;
    cfg.stream = 0;
    cudaLaunchAttribute attr[1];
    attr[0].id = cudaLaunchAttributeProgrammaticStreamSerialization;
    attr[0].val.programmaticStreamSerializationAllowed = 1;
    cfg.attrs = attr;
    cfg.numAttrs = 1;
    cudaLaunchKernelEx(&cfg, pair_kernel, xyz, cell, out);
}